// round 9
// baseline (speedup 1.0000x reference)
#include <cuda_runtime.h>
#include <cuda_fp16.h>
#include <cstdint>
#include <math.h>

#define NB   4
#define SEQ  4096
#define EMB  1024
#define HID  4096
#define NTOK (NB * SEQ)   // 16384

// ======================= helpers ==============================================
__device__ __forceinline__ uint32_t smem_u32(const void* p) {
    uint32_t a;
    asm("{ .reg .u64 t; cvta.to.shared.u64 t, %1; cvt.u32.u64 %0, t; }" : "=r"(a) : "l"(p));
    return a;
}
// SW64 swizzle for 64-byte rows (conflict-free for 16B cp.async + ldmatrix)
__device__ __forceinline__ uint32_t swz64(uint32_t o) { return o ^ ((o >> 3) & 0x30); }

__device__ __forceinline__ void cp_async16(uint32_t dst, const void* src) {
    asm volatile("cp.async.cg.shared.global [%0], [%1], 16;" :: "r"(dst), "l"(src));
}
#define CP_COMMIT() asm volatile("cp.async.commit_group;" ::: "memory")
#define CP_WAIT3()  asm volatile("cp.async.wait_group 3;" ::: "memory")

__device__ __forceinline__ void ldmx4(uint32_t r[4], uint32_t addr) {
    asm volatile("ldmatrix.sync.aligned.m8n8.x4.shared.b16 {%0,%1,%2,%3}, [%4];"
                 : "=r"(r[0]), "=r"(r[1]), "=r"(r[2]), "=r"(r[3]) : "r"(addr));
}
__device__ __forceinline__ void mma16816(float d[4], const uint32_t a[4],
                                         uint32_t b0, uint32_t b1) {
    asm volatile("mma.sync.aligned.m16n8k16.row.col.f32.f16.f16.f32 "
                 "{%0,%1,%2,%3}, {%4,%5,%6,%7}, {%8,%9}, {%0,%1,%2,%3};"
                 : "+f"(d[0]), "+f"(d[1]), "+f"(d[2]), "+f"(d[3])
                 : "r"(a[0]), "r"(a[1]), "r"(a[2]), "r"(a[3]), "r"(b0), "r"(b1));
}

// ======================= device scratch =======================================
__device__ float g_wvs [EMB * 64];
__device__ __align__(16) __half g_vsh [EMB * EMB];              // vsum fp16 (1024x1024 view)
__device__ __align__(16) __half g_woT [EMB * EMB];              // w_o^T fp16
__device__ float g_A   [NB * 256 * EMB];
__device__ float g_h1  [(long long)NTOK * EMB];                 // fp32 residual
__device__ __align__(16) __half g_h1f [(long long)NTOK * EMB];  // h1 fp16
__device__ __align__(16) __half g_ff1 [(long long)NTOK * HID];  // relu(ff1) fp16
__device__ __align__(16) __half g_w1t [(long long)HID * EMB];   // w_ff1^T fp16
__device__ __align__(16) __half g_w2t [(long long)EMB * HID];   // w_ff2^T fp16
__device__ float g_y   [(long long)NTOK * EMB];

// ======================= fold w_v over heads ==================================
__global__ void fold_wv_kernel(const float* __restrict__ wv) {
    int idx = blockIdx.x * blockDim.x + threadIdx.x;
    if (idx >= EMB * 64) return;
    int e = idx >> 6, d = idx & 63;
    float s = 0.f;
#pragma unroll
    for (int j = 0; j < 16; j++) s += wv[e * EMB + j * 64 + d];
    g_wvs[idx] = s;
}

// ============== transpose + fp16 convert: src(R,C) -> dst(C,R) ================
__global__ void transpose_cvt(const float* __restrict__ src,
                              __half* __restrict__ dst, int R, int C) {
    __shared__ float tile[32][33];
    int r = blockIdx.y * 32 + threadIdx.y;
    int c = blockIdx.x * 32 + threadIdx.x;
    tile[threadIdx.y][threadIdx.x] = src[(size_t)r * C + c];
    __syncthreads();
    int orow = blockIdx.x * 32 + threadIdx.y;
    int ocol = blockIdx.y * 32 + threadIdx.x;
    dst[(size_t)orow * R + ocol] = __float2half(tile[threadIdx.x][threadIdx.y]);
}

// ====== Vsum = x @ Wvs : (16384,1024)@(1024,64), fp16 out =====================
__global__ __launch_bounds__(256)
void vsum_kernel(const float* __restrict__ x) {
    __shared__ float  As[32][33];
    __shared__ float4 Bs[32][16];
    const int tid = threadIdx.x;
    const int base = blockIdx.x * 32;
    const int tx = tid & 15, ty = tid >> 4;
    float acc[2][4] = {};
    const int lr = tid >> 3, lc4 = (tid & 7) * 4;
    for (int k0 = 0; k0 < EMB; k0 += 32) {
        float4 a4 = *(const float4*)(x + (size_t)(base + lr) * EMB + k0 + lc4);
        As[lr][lc4 + 0] = a4.x; As[lr][lc4 + 1] = a4.y;
        As[lr][lc4 + 2] = a4.z; As[lr][lc4 + 3] = a4.w;
#pragma unroll
        for (int i = 0; i < 2; i++) {
            int f = tid * 2 + i;
            int row = f >> 4, col4 = f & 15;
            Bs[row][col4] = ((const float4*)g_wvs)[(size_t)(k0 + row) * 16 + col4];
        }
        __syncthreads();
#pragma unroll
        for (int ks = 0; ks < 32; ks++) {
            float a0 = As[ty * 2 + 0][ks];
            float a1 = As[ty * 2 + 1][ks];
            float4 b4 = Bs[ks][tx];
            acc[0][0] += a0 * b4.x; acc[0][1] += a0 * b4.y;
            acc[0][2] += a0 * b4.z; acc[0][3] += a0 * b4.w;
            acc[1][0] += a1 * b4.x; acc[1][1] += a1 * b4.y;
            acc[1][2] += a1 * b4.z; acc[1][3] += a1 * b4.w;
        }
        __syncthreads();
    }
#pragma unroll
    for (int i = 0; i < 2; i++) {
        const size_t o = (size_t)(base + ty * 2 + i) * 64 + tx * 4;
        __align__(8) __half h4[4];
        h4[0] = __float2half(acc[i][0]); h4[1] = __float2half(acc[i][1]);
        h4[2] = __float2half(acc[i][2]); h4[3] = __float2half(acc[i][3]);
        *(uint2*)(g_vsh + o) = *(uint2*)h4;
    }
}

// ================= HMMA fp16 GEMM =============================================
// C = A(M,K) @ B(N,K)^T, fp16 in, fp32 accum. CTA tile 128x128x32.
// 4 warps (2x2 grid), warp tile 64x64 — A/B fragments each duplicated only x2.
// 4-stage cp.async pipeline, 16KB/stage; 128 threads, 2 CTAs/SM.
// G1: out = relu(C+bias) -> fp16.  !G1: out = C+bias (+res if RES) -> fp32.
#define STG_BYTES 16384
template <bool G1, bool RES>
__global__ __launch_bounds__(128)
void gemm_mma(const __half* __restrict__ A, const __half* __restrict__ B,
              const float* __restrict__ bias, const float* __restrict__ res,
              __half* __restrict__ Oh, float* __restrict__ Of, int K, int N) {
    extern __shared__ char smem[];
    const uint32_t sb = smem_u32(smem);
    const int tid  = threadIdx.x;
    const int lane = tid & 31;
    const int wid  = tid >> 5;
    const int wm = wid >> 1;          // 0..1  (64-row slab)
    const int wn = wid & 1;           // 0..1  (64-col slab)
    const int bx = blockIdx.x, by = blockIdx.y;

    // ---- loader mapping: 128 threads; per 8KB array each thread does 4x16B ---
    // rows lr and lr+64, granules lg and lg+1 of each row.
    const int lr = tid >> 1, lg = (tid & 1) * 2;
    const uint32_t sA00 = lr * 64        + (((lg + 0) ^ ((lr >> 1) & 3)) << 4);
    const uint32_t sA01 = lr * 64        + (((lg + 1) ^ ((lr >> 1) & 3)) << 4);
    const uint32_t sA10 = (lr + 64) * 64 + (((lg + 0) ^ (((lr + 64) >> 1) & 3)) << 4);
    const uint32_t sA11 = (lr + 64) * 64 + (((lg + 1) ^ (((lr + 64) >> 1) & 3)) << 4);
    const size_t arow0 = (size_t)(by * 128 + lr) * K;
    const size_t arow1 = (size_t)(by * 128 + lr + 64) * K;
    const size_t brow0 = (size_t)(bx * 128 + lr) * K;
    const size_t brow1 = (size_t)(bx * 128 + lr + 64) * K;
    const int ke0 = lg * 8, ke1 = lg * 8 + 8;

    const int NC = K / 32;
    auto load_stage = [&](int c, int s) {
        const uint32_t st = sb + s * STG_BYTES;
        const int kc = c * 32;
        cp_async16(st +        sA00, A + arow0 + kc + ke0);
        cp_async16(st +        sA01, A + arow0 + kc + ke1);
        cp_async16(st +        sA10, A + arow1 + kc + ke0);
        cp_async16(st +        sA11, A + arow1 + kc + ke1);
        cp_async16(st + 8192 + sA00, B + brow0 + kc + ke0);
        cp_async16(st + 8192 + sA01, B + brow0 + kc + ke1);
        cp_async16(st + 8192 + sA10, B + brow1 + kc + ke0);
        cp_async16(st + 8192 + sA11, B + brow1 + kc + ke1);
        CP_COMMIT();
    };

    load_stage(0, 0); load_stage(1, 1); load_stage(2, 2); load_stage(3, 3);

    // ---- ldmatrix lane addressing -------------------------------------------
    const int lr8 = lane & 7, l8 = (lane >> 3) & 1, l16 = (lane >> 4) & 1;
    const int frow = lr8 + l8 * 8;
    const int fkb  = l16 * 16;

    float acc[4][8][4] = {};

    for (int c = 0; c < NC; c++) {
        const int s = c & 3;
        CP_WAIT3();
        __syncthreads();
        const uint32_t st = sb + s * STG_BYTES;
#pragma unroll
        for (int ks = 0; ks < 2; ks++) {
            const int kb = ks * 32 + fkb;
            uint32_t ah[4][4], b[8][2];
#pragma unroll
            for (int mi = 0; mi < 4; mi++) {
                const uint32_t off = swz64((wm * 64 + mi * 16 + frow) * 64 + kb);
                ldmx4(ah[mi], st + off);
            }
#pragma unroll
            for (int nt = 0; nt < 4; nt++) {
                const uint32_t off = swz64((wn * 64 + nt * 16 + frow) * 64 + kb);
                uint32_t q[4];
                ldmx4(q, st + 8192 + off);
                b[nt*2][0] = q[0]; b[nt*2+1][0] = q[1];
                b[nt*2][1] = q[2]; b[nt*2+1][1] = q[3];
            }
#pragma unroll
            for (int mi = 0; mi < 4; mi++)
#pragma unroll
                for (int j = 0; j < 8; j++)
                    mma16816(acc[mi][j], ah[mi], b[j][0], b[j][1]);
        }
        __syncthreads();
        if (c + 4 < NC) load_stage(c + 4, s);
    }

    // ---- epilogue ------------------------------------------------------------
    const int g = lane >> 2, tg = lane & 3;
#pragma unroll
    for (int mi = 0; mi < 4; mi++) {
#pragma unroll
        for (int j = 0; j < 8; j++) {
            const int col = bx * 128 + wn * 64 + j * 8 + tg * 2;
            const float2 b2 = *(const float2*)(bias + col);
#pragma unroll
            for (int hrow = 0; hrow < 2; hrow++) {
                const size_t row = (size_t)(by * 128 + wm * 64 + mi * 16 + g + hrow * 8);
                float v0 = acc[mi][j][hrow * 2 + 0] + b2.x;
                float v1 = acc[mi][j][hrow * 2 + 1] + b2.y;
                if (G1) {
                    v0 = fmaxf(v0, 0.f); v1 = fmaxf(v1, 0.f);
                    __half2 hh;
                    hh.x = __float2half(v0); hh.y = __float2half(v1);
                    *(__half2*)(Oh + row * N + col) = hh;
                } else {
                    float2 o = make_float2(v0, v1);
                    if (RES) {
                        const float2 rv = *(const float2*)(res + row * N + col);
                        o.x += rv.x; o.y += rv.y;
                    }
                    *(float2*)(Of + row * N + col) = o;
                }
            }
        }
    }
}

// ======================= LayerNorm kernels ====================================
__device__ __forceinline__ void block_reduce2(float& s, float& q) {
#pragma unroll
    for (int off = 16; off; off >>= 1) {
        s += __shfl_xor_sync(0xffffffffu, s, off);
        q += __shfl_xor_sync(0xffffffffu, q, off);
    }
    __shared__ float sh_s[8], sh_q[8];
    int w = threadIdx.x >> 5;
    if ((threadIdx.x & 31) == 0) { sh_s[w] = s; sh_q[w] = q; }
    __syncthreads();
    s = 0.f; q = 0.f;
#pragma unroll
    for (int i = 0; i < 8; i++) { s += sh_s[i]; q += sh_q[i]; }
}

__global__ void ln1_kernel(const float* __restrict__ x,
                           const float* __restrict__ w, const float* __restrict__ b) {
    int t = blockIdx.x;
    int n = t >> 12, l = t & (SEQ - 1);
    int c = threadIdx.x;
    float4 xv = ((const float4*)(x + (size_t)t * EMB))[c];
    float4 av = ((const float4*)(g_A + (size_t)(n * 256 + (l & 255)) * EMB))[c];
    float v0 = xv.x + av.x, v1 = xv.y + av.y, v2 = xv.z + av.z, v3 = xv.w + av.w;
    float s = v0 + v1 + v2 + v3;
    float q = v0 * v0 + v1 * v1 + v2 * v2 + v3 * v3;
    block_reduce2(s, q);
    float mu  = s * (1.f / EMB);
    float var = q * (1.f / EMB) - mu * mu;
    float rs  = rsqrtf(var + 1e-5f);
    float4 wv = ((const float4*)w)[c], bv = ((const float4*)b)[c];
    float4 o;
    o.x = (v0 - mu) * rs * wv.x + bv.x;
    o.y = (v1 - mu) * rs * wv.y + bv.y;
    o.z = (v2 - mu) * rs * wv.z + bv.z;
    o.w = (v3 - mu) * rs * wv.w + bv.w;
    ((float4*)(g_h1 + (size_t)t * EMB))[c] = o;
    __align__(8) __half h4[4];
    h4[0] = __float2half(o.x); h4[1] = __float2half(o.y);
    h4[2] = __float2half(o.z); h4[3] = __float2half(o.w);
    ((uint2*)(g_h1f + (size_t)t * EMB))[c] = *(uint2*)h4;
}

__global__ void ln2_kernel(const float* __restrict__ w, const float* __restrict__ b,
                           float* __restrict__ out) {
    int t = blockIdx.x;
    int c = threadIdx.x;
    float4 yv = ((const float4*)(g_y + (size_t)t * EMB))[c];
    float v0 = yv.x, v1 = yv.y, v2 = yv.z, v3 = yv.w;
    float s = v0 + v1 + v2 + v3;
    float q = v0 * v0 + v1 * v1 + v2 * v2 + v3 * v3;
    block_reduce2(s, q);
    float mu  = s * (1.f / EMB);
    float var = q * (1.f / EMB) - mu * mu;
    float rs  = rsqrtf(var + 1e-5f);
    float4 wv = ((const float4*)w)[c], bv = ((const float4*)b)[c];
    float4 o;
    o.x = (v0 - mu) * rs * wv.x + bv.x;
    o.y = (v1 - mu) * rs * wv.y + bv.y;
    o.z = (v2 - mu) * rs * wv.z + bv.z;
    o.w = (v3 - mu) * rs * wv.w + bv.w;
    ((float4*)(out + (size_t)t * EMB))[c] = o;
}

// ==============================================================================
extern "C" void kernel_launch(void* const* d_in, const int* in_sizes, int n_in,
                              void* d_out, int out_size) {
    const float* x     = (const float*)d_in[0];
    const float* w_v   = (const float*)d_in[3];
    const float* w_o   = (const float*)d_in[4];
    const float* b_o   = (const float*)d_in[5];
    const float* ln1_w = (const float*)d_in[6];
    const float* ln1_b = (const float*)d_in[7];
    const float* ln2_w = (const float*)d_in[8];
    const float* ln2_b = (const float*)d_in[9];
    const float* w_ff1 = (const float*)d_in[10];
    const float* b_ff1 = (const float*)d_in[11];
    const float* w_ff2 = (const float*)d_in[12];
    const float* b_ff2 = (const float*)d_in[13];
    float* out = (float*)d_out;

    float *A, *h1, *y;
    __half *vsh, *woT, *h1f, *ff1, *w1t, *w2t;
    cudaGetSymbolAddress((void**)&A,   g_A);
    cudaGetSymbolAddress((void**)&h1,  g_h1);
    cudaGetSymbolAddress((void**)&y,   g_y);
    cudaGetSymbolAddress((void**)&vsh, g_vsh);
    cudaGetSymbolAddress((void**)&woT, g_woT);
    cudaGetSymbolAddress((void**)&h1f, g_h1f);
    cudaGetSymbolAddress((void**)&ff1, g_ff1);
    cudaGetSymbolAddress((void**)&w1t, g_w1t);
    cudaGetSymbolAddress((void**)&w2t, g_w2t);

    const int GEMM_SMEM = 4 * STG_BYTES;   // 64 KB
    cudaFuncSetAttribute(gemm_mma<true,false>,  cudaFuncAttributeMaxDynamicSharedMemorySize, GEMM_SMEM);
    cudaFuncSetAttribute(gemm_mma<false,true>,  cudaFuncAttributeMaxDynamicSharedMemorySize, GEMM_SMEM);
    cudaFuncSetAttribute(gemm_mma<false,false>, cudaFuncAttributeMaxDynamicSharedMemorySize, GEMM_SMEM);

    // 1) prep: fold w_v; transpose+convert weights to K-major fp16
    fold_wv_kernel<<<(EMB * 64 + 255) / 256, 256>>>(w_v);
    transpose_cvt<<<dim3(EMB / 32, EMB / 32), dim3(32, 32)>>>(w_o,   woT, EMB, EMB);
    transpose_cvt<<<dim3(HID / 32, EMB / 32), dim3(32, 32)>>>(w_ff1, w1t, EMB, HID);
    transpose_cvt<<<dim3(EMB / 32, HID / 32), dim3(32, 32)>>>(w_ff2, w2t, HID, EMB);

    // 2) Vsum = x @ Wvs -> fp16 (1024x1024 view)
    vsum_kernel<<<NTOK / 32, 256>>>(x);

    // 3) A = Vsum @ w_o + b_o   [HMMA fp16]
    gemm_mma<false,false><<<dim3(EMB / 128, EMB / 128), 128, GEMM_SMEM>>>(
        vsh, woT, b_o, nullptr, nullptr, A, EMB, EMB);

    // 4) h1 = LN1(x + A[n, l%256])  (+ fp16 copy)
    ln1_kernel<<<NTOK, 256>>>(x, ln1_w, ln1_b);

    // 5) ff1 = relu(h1 @ w_ff1 + b_ff1) -> fp16   [HMMA fp16]
    gemm_mma<true,false><<<dim3(HID / 128, NTOK / 128), 128, GEMM_SMEM>>>(
        h1f, w1t, b_ff1, nullptr, ff1, nullptr, EMB, HID);

    // 6) y = ff1 @ w_ff2 + b_ff2 + h1 -> fp32      [HMMA fp16]
    gemm_mma<false,true><<<dim3(EMB / 128, NTOK / 128), 128, GEMM_SMEM>>>(
        ff1, w2t, b_ff2, h1, nullptr, y, HID, EMB);

    // 7) out = LN2(y)
    ln2_kernel<<<NTOK, 256>>>(ln2_w, ln2_b, out);
}

// round 11
// speedup vs baseline: 1.1840x; 1.1840x over previous
#include <cuda_runtime.h>
#include <cuda_fp16.h>
#include <cstdint>
#include <math.h>

#define NB   4
#define SEQ  4096
#define EMB  1024
#define HID  4096
#define NTOK (NB * SEQ)   // 16384

// ======================= helpers ==============================================
__device__ __forceinline__ uint32_t smem_u32(const void* p) {
    uint32_t a;
    asm("{ .reg .u64 t; cvta.to.shared.u64 t, %1; cvt.u32.u64 %0, t; }" : "=r"(a) : "l"(p));
    return a;
}
// SW64 swizzle for 64-byte rows (conflict-free for 16B cp.async + ldmatrix)
__device__ __forceinline__ uint32_t swz64(uint32_t o) { return o ^ ((o >> 3) & 0x30); }

__device__ __forceinline__ void cp_async16(uint32_t dst, const void* src) {
    asm volatile("cp.async.cg.shared.global [%0], [%1], 16;" :: "r"(dst), "l"(src));
}
#define CP_COMMIT() asm volatile("cp.async.commit_group;" ::: "memory")
#define CP_WAIT3()  asm volatile("cp.async.wait_group 3;" ::: "memory")
#define CP_WAIT0()  asm volatile("cp.async.wait_group 0;" ::: "memory")

__device__ __forceinline__ void ldmx4(uint32_t r[4], uint32_t addr) {
    asm volatile("ldmatrix.sync.aligned.m8n8.x4.shared.b16 {%0,%1,%2,%3}, [%4];"
                 : "=r"(r[0]), "=r"(r[1]), "=r"(r[2]), "=r"(r[3]) : "r"(addr));
}
__device__ __forceinline__ void mma16816(float d[4], const uint32_t a[4],
                                         uint32_t b0, uint32_t b1) {
    asm volatile("mma.sync.aligned.m16n8k16.row.col.f32.f16.f16.f32 "
                 "{%0,%1,%2,%3}, {%4,%5,%6,%7}, {%8,%9}, {%0,%1,%2,%3};"
                 : "+f"(d[0]), "+f"(d[1]), "+f"(d[2]), "+f"(d[3])
                 : "r"(a[0]), "r"(a[1]), "r"(a[2]), "r"(a[3]), "r"(b0), "r"(b1));
}

// ======================= device scratch =======================================
__device__ float g_wvs [EMB * 64];
__device__ __align__(16) __half g_vsh [EMB * EMB];              // vsum fp16 (1024x1024 view)
__device__ __align__(16) __half g_woT [EMB * EMB];              // w_o^T fp16
__device__ float g_A   [NB * 256 * EMB];
__device__ float g_h1  [(long long)NTOK * EMB];                 // fp32 residual
__device__ __align__(16) __half g_h1f [(long long)NTOK * EMB];  // h1 fp16
__device__ __align__(16) __half g_ff1 [(long long)NTOK * HID];  // relu(ff1) fp16
__device__ __align__(16) __half g_w1t [(long long)HID * EMB];   // w_ff1^T fp16
__device__ __align__(16) __half g_w2t [(long long)EMB * HID];   // w_ff2^T fp16
__device__ float g_y   [(long long)NTOK * EMB];

// ======================= fold w_v over heads ==================================
__global__ void fold_wv_kernel(const float* __restrict__ wv) {
    int idx = blockIdx.x * blockDim.x + threadIdx.x;
    if (idx >= EMB * 64) return;
    int e = idx >> 6, d = idx & 63;
    float s = 0.f;
#pragma unroll
    for (int j = 0; j < 16; j++) s += wv[e * EMB + j * 64 + d];
    g_wvs[idx] = s;
}

// ============== transpose + fp16 convert: src(R,C) -> dst(C,R) ================
__global__ void transpose_cvt(const float* __restrict__ src,
                              __half* __restrict__ dst, int R, int C) {
    __shared__ float tile[32][33];
    int r = blockIdx.y * 32 + threadIdx.y;
    int c = blockIdx.x * 32 + threadIdx.x;
    tile[threadIdx.y][threadIdx.x] = src[(size_t)r * C + c];
    __syncthreads();
    int orow = blockIdx.x * 32 + threadIdx.y;
    int ocol = blockIdx.y * 32 + threadIdx.x;
    dst[(size_t)orow * R + ocol] = __float2half(tile[threadIdx.x][threadIdx.y]);
}

// ====== Vsum = x @ Wvs : (16384,1024)@(1024,64), fp16 out =====================
__global__ __launch_bounds__(256)
void vsum_kernel(const float* __restrict__ x) {
    __shared__ float  As[32][33];
    __shared__ float4 Bs[32][16];
    const int tid = threadIdx.x;
    const int base = blockIdx.x * 32;
    const int tx = tid & 15, ty = tid >> 4;
    float acc[2][4] = {};
    const int lr = tid >> 3, lc4 = (tid & 7) * 4;
    for (int k0 = 0; k0 < EMB; k0 += 32) {
        float4 a4 = *(const float4*)(x + (size_t)(base + lr) * EMB + k0 + lc4);
        As[lr][lc4 + 0] = a4.x; As[lr][lc4 + 1] = a4.y;
        As[lr][lc4 + 2] = a4.z; As[lr][lc4 + 3] = a4.w;
#pragma unroll
        for (int i = 0; i < 2; i++) {
            int f = tid * 2 + i;
            int row = f >> 4, col4 = f & 15;
            Bs[row][col4] = ((const float4*)g_wvs)[(size_t)(k0 + row) * 16 + col4];
        }
        __syncthreads();
#pragma unroll
        for (int ks = 0; ks < 32; ks++) {
            float a0 = As[ty * 2 + 0][ks];
            float a1 = As[ty * 2 + 1][ks];
            float4 b4 = Bs[ks][tx];
            acc[0][0] += a0 * b4.x; acc[0][1] += a0 * b4.y;
            acc[0][2] += a0 * b4.z; acc[0][3] += a0 * b4.w;
            acc[1][0] += a1 * b4.x; acc[1][1] += a1 * b4.y;
            acc[1][2] += a1 * b4.z; acc[1][3] += a1 * b4.w;
        }
        __syncthreads();
    }
#pragma unroll
    for (int i = 0; i < 2; i++) {
        const size_t o = (size_t)(base + ty * 2 + i) * 64 + tx * 4;
        __align__(8) __half h4[4];
        h4[0] = __float2half(acc[i][0]); h4[1] = __float2half(acc[i][1]);
        h4[2] = __float2half(acc[i][2]); h4[3] = __float2half(acc[i][3]);
        *(uint2*)(g_vsh + o) = *(uint2*)h4;
    }
}

// ================= HMMA fp16 GEMM =============================================
// C = A(M,K) @ B(N,K)^T, fp16 in, fp32 accum. CTA tile 128x128x32,
// 8 warps (2x4 grid), warp tile 64x32, 256 threads (proven R6 geometry).
// 5-slot cp.async ring, ONE barrier per chunk:
//   wait_group 3 -> __syncthreads -> load(c+4) -> compute(c)
// The barrier both publishes stage c and proves compute(c-1) released the slot
// that load(c+4) overwrites ((c+4)%5 == (c-1)%5). Tail uses wait_group 0
// (fixes latent R6 race where <4 pending groups made wait_group 3 a no-op).
#define STG_BYTES 16384
#define N_STAGES  5
template <bool G1, bool RES>
__global__ __launch_bounds__(256)
void gemm_mma(const __half* __restrict__ A, const __half* __restrict__ B,
              const float* __restrict__ bias, const float* __restrict__ res,
              __half* __restrict__ Oh, float* __restrict__ Of, int K, int N) {
    extern __shared__ char smem[];
    const uint32_t sb = smem_u32(smem);
    const int tid  = threadIdx.x;
    const int lane = tid & 31;
    const int wid  = tid >> 5;
    const int wm = wid >> 2;          // 0..1  (64-row slab)
    const int wn = wid & 3;           // 0..3  (32-col slab)
    const int bx = blockIdx.x, by = blockIdx.y;

    // ---- loader mapping: 256 threads, 4 x 16B each per stage ----------------
    const int lr = tid >> 2, lg = tid & 3;
    const uint32_t sd0 = lr * 64 + ((lg ^ ((lr >> 1) & 3)) << 4);
    const uint32_t sd1 = (lr + 64) * 64 + ((lg ^ (((lr + 64) >> 1) & 3)) << 4);
    const size_t arow0 = (size_t)(by * 128 + lr) * K;
    const size_t arow1 = (size_t)(by * 128 + lr + 64) * K;
    const size_t brow0 = (size_t)(bx * 128 + lr) * K;
    const size_t brow1 = (size_t)(bx * 128 + lr + 64) * K;
    const int kel = lg * 8;

    const int NC = K / 32;
    auto load_stage = [&](int c, int s) {
        const uint32_t st = sb + s * STG_BYTES;
        const int kc = c * 32 + kel;
        cp_async16(st +        sd0, A + arow0 + kc);
        cp_async16(st +        sd1, A + arow1 + kc);
        cp_async16(st + 8192 + sd0, B + brow0 + kc);
        cp_async16(st + 8192 + sd1, B + brow1 + kc);
        CP_COMMIT();
    };

    // prologue: fill 4 of 5 slots
    load_stage(0, 0); load_stage(1, 1); load_stage(2, 2); load_stage(3, 3);

    // ---- ldmatrix lane addressing -------------------------------------------
    const int lr8 = lane & 7, l8 = (lane >> 3) & 1, l16 = (lane >> 4) & 1;
    const int frow = lr8 + l8 * 8;
    const int fkb  = l16 * 16;

    float acc[4][4][4] = {};

    for (int c = 0; c < NC; c++) {
        const int s = c % N_STAGES;
        if (c + 4 < NC) CP_WAIT3(); else CP_WAIT0();
        __syncthreads();
        if (c + 4 < NC) load_stage(c + 4, (c + 4) % N_STAGES);
        const uint32_t st = sb + s * STG_BYTES;
#pragma unroll
        for (int ks = 0; ks < 2; ks++) {
            const int kb = ks * 32 + fkb;
            uint32_t ah[4][4], b[4][2];
#pragma unroll
            for (int mi = 0; mi < 4; mi++) {
                const uint32_t off = swz64((wm * 64 + mi * 16 + frow) * 64 + kb);
                ldmx4(ah[mi], st + off);
            }
#pragma unroll
            for (int nt = 0; nt < 2; nt++) {
                const uint32_t off = swz64((wn * 32 + nt * 16 + frow) * 64 + kb);
                uint32_t q[4];
                ldmx4(q, st + 8192 + off);
                b[nt*2][0] = q[0]; b[nt*2+1][0] = q[1];
                b[nt*2][1] = q[2]; b[nt*2+1][1] = q[3];
            }
#pragma unroll
            for (int mi = 0; mi < 4; mi++)
#pragma unroll
                for (int j = 0; j < 4; j++)
                    mma16816(acc[mi][j], ah[mi], b[j][0], b[j][1]);
        }
        // no trailing barrier: next iteration's barrier protects slot reuse
    }

    // ---- epilogue ------------------------------------------------------------
    const int g = lane >> 2, tg = lane & 3;
#pragma unroll
    for (int mi = 0; mi < 4; mi++) {
#pragma unroll
        for (int j = 0; j < 4; j++) {
            const int col = bx * 128 + wn * 32 + j * 8 + tg * 2;
            const float2 b2 = *(const float2*)(bias + col);
#pragma unroll
            for (int hrow = 0; hrow < 2; hrow++) {
                const size_t row = (size_t)(by * 128 + wm * 64 + mi * 16 + g + hrow * 8);
                float v0 = acc[mi][j][hrow * 2 + 0] + b2.x;
                float v1 = acc[mi][j][hrow * 2 + 1] + b2.y;
                if (G1) {
                    v0 = fmaxf(v0, 0.f); v1 = fmaxf(v1, 0.f);
                    __half2 hh;
                    hh.x = __float2half(v0); hh.y = __float2half(v1);
                    *(__half2*)(Oh + row * N + col) = hh;
                } else {
                    float2 o = make_float2(v0, v1);
                    if (RES) {
                        const float2 rv = *(const float2*)(res + row * N + col);
                        o.x += rv.x; o.y += rv.y;
                    }
                    *(float2*)(Of + row * N + col) = o;
                }
            }
        }
    }
}

// ======================= LayerNorm kernels ====================================
__device__ __forceinline__ void block_reduce2(float& s, float& q) {
#pragma unroll
    for (int off = 16; off; off >>= 1) {
        s += __shfl_xor_sync(0xffffffffu, s, off);
        q += __shfl_xor_sync(0xffffffffu, q, off);
    }
    __shared__ float sh_s[8], sh_q[8];
    int w = threadIdx.x >> 5;
    if ((threadIdx.x & 31) == 0) { sh_s[w] = s; sh_q[w] = q; }
    __syncthreads();
    s = 0.f; q = 0.f;
#pragma unroll
    for (int i = 0; i < 8; i++) { s += sh_s[i]; q += sh_q[i]; }
}

__global__ void ln1_kernel(const float* __restrict__ x,
                           const float* __restrict__ w, const float* __restrict__ b) {
    int t = blockIdx.x;
    int n = t >> 12, l = t & (SEQ - 1);
    int c = threadIdx.x;
    float4 xv = ((const float4*)(x + (size_t)t * EMB))[c];
    float4 av = ((const float4*)(g_A + (size_t)(n * 256 + (l & 255)) * EMB))[c];
    float v0 = xv.x + av.x, v1 = xv.y + av.y, v2 = xv.z + av.z, v3 = xv.w + av.w;
    float s = v0 + v1 + v2 + v3;
    float q = v0 * v0 + v1 * v1 + v2 * v2 + v3 * v3;
    block_reduce2(s, q);
    float mu  = s * (1.f / EMB);
    float var = q * (1.f / EMB) - mu * mu;
    float rs  = rsqrtf(var + 1e-5f);
    float4 wv = ((const float4*)w)[c], bv = ((const float4*)b)[c];
    float4 o;
    o.x = (v0 - mu) * rs * wv.x + bv.x;
    o.y = (v1 - mu) * rs * wv.y + bv.y;
    o.z = (v2 - mu) * rs * wv.z + bv.z;
    o.w = (v3 - mu) * rs * wv.w + bv.w;
    ((float4*)(g_h1 + (size_t)t * EMB))[c] = o;
    __align__(8) __half h4[4];
    h4[0] = __float2half(o.x); h4[1] = __float2half(o.y);
    h4[2] = __float2half(o.z); h4[3] = __float2half(o.w);
    ((uint2*)(g_h1f + (size_t)t * EMB))[c] = *(uint2*)h4;
}

__global__ void ln2_kernel(const float* __restrict__ w, const float* __restrict__ b,
                           float* __restrict__ out) {
    int t = blockIdx.x;
    int c = threadIdx.x;
    float4 yv = ((const float4*)(g_y + (size_t)t * EMB))[c];
    float v0 = yv.x, v1 = yv.y, v2 = yv.z, v3 = yv.w;
    float s = v0 + v1 + v2 + v3;
    float q = v0 * v0 + v1 * v1 + v2 * v2 + v3 * v3;
    block_reduce2(s, q);
    float mu  = s * (1.f / EMB);
    float var = q * (1.f / EMB) - mu * mu;
    float rs  = rsqrtf(var + 1e-5f);
    float4 wv = ((const float4*)w)[c], bv = ((const float4*)b)[c];
    float4 o;
    o.x = (v0 - mu) * rs * wv.x + bv.x;
    o.y = (v1 - mu) * rs * wv.y + bv.y;
    o.z = (v2 - mu) * rs * wv.z + bv.z;
    o.w = (v3 - mu) * rs * wv.w + bv.w;
    ((float4*)(out + (size_t)t * EMB))[c] = o;
}

// ==============================================================================
extern "C" void kernel_launch(void* const* d_in, const int* in_sizes, int n_in,
                              void* d_out, int out_size) {
    const float* x     = (const float*)d_in[0];
    const float* w_v   = (const float*)d_in[3];
    const float* w_o   = (const float*)d_in[4];
    const float* b_o   = (const float*)d_in[5];
    const float* ln1_w = (const float*)d_in[6];
    const float* ln1_b = (const float*)d_in[7];
    const float* ln2_w = (const float*)d_in[8];
    const float* ln2_b = (const float*)d_in[9];
    const float* w_ff1 = (const float*)d_in[10];
    const float* b_ff1 = (const float*)d_in[11];
    const float* w_ff2 = (const float*)d_in[12];
    const float* b_ff2 = (const float*)d_in[13];
    float* out = (float*)d_out;

    float *A, *h1, *y;
    __half *vsh, *woT, *h1f, *ff1, *w1t, *w2t;
    cudaGetSymbolAddress((void**)&A,   g_A);
    cudaGetSymbolAddress((void**)&h1,  g_h1);
    cudaGetSymbolAddress((void**)&y,   g_y);
    cudaGetSymbolAddress((void**)&vsh, g_vsh);
    cudaGetSymbolAddress((void**)&woT, g_woT);
    cudaGetSymbolAddress((void**)&h1f, g_h1f);
    cudaGetSymbolAddress((void**)&ff1, g_ff1);
    cudaGetSymbolAddress((void**)&w1t, g_w1t);
    cudaGetSymbolAddress((void**)&w2t, g_w2t);

    const int GEMM_SMEM = N_STAGES * STG_BYTES;   // 80 KB
    cudaFuncSetAttribute(gemm_mma<true,false>,  cudaFuncAttributeMaxDynamicSharedMemorySize, GEMM_SMEM);
    cudaFuncSetAttribute(gemm_mma<false,true>,  cudaFuncAttributeMaxDynamicSharedMemorySize, GEMM_SMEM);
    cudaFuncSetAttribute(gemm_mma<false,false>, cudaFuncAttributeMaxDynamicSharedMemorySize, GEMM_SMEM);

    // 1) prep: fold w_v; transpose+convert weights to K-major fp16
    fold_wv_kernel<<<(EMB * 64 + 255) / 256, 256>>>(w_v);
    transpose_cvt<<<dim3(EMB / 32, EMB / 32), dim3(32, 32)>>>(w_o,   woT, EMB, EMB);
    transpose_cvt<<<dim3(HID / 32, EMB / 32), dim3(32, 32)>>>(w_ff1, w1t, EMB, HID);
    transpose_cvt<<<dim3(EMB / 32, HID / 32), dim3(32, 32)>>>(w_ff2, w2t, HID, EMB);

    // 2) Vsum = x @ Wvs -> fp16 (1024x1024 view)
    vsum_kernel<<<NTOK / 32, 256>>>(x);

    // 3) A = Vsum @ w_o + b_o   [HMMA fp16]
    gemm_mma<false,false><<<dim3(EMB / 128, EMB / 128), 256, GEMM_SMEM>>>(
        vsh, woT, b_o, nullptr, nullptr, A, EMB, EMB);

    // 4) h1 = LN1(x + A[n, l%256])  (+ fp16 copy)
    ln1_kernel<<<NTOK, 256>>>(x, ln1_w, ln1_b);

    // 5) ff1 = relu(h1 @ w_ff1 + b_ff1) -> fp16   [HMMA fp16]
    gemm_mma<true,false><<<dim3(HID / 128, NTOK / 128), 256, GEMM_SMEM>>>(
        h1f, w1t, b_ff1, nullptr, ff1, nullptr, EMB, HID);

    // 6) y = ff1 @ w_ff2 + b_ff2 + h1 -> fp32      [HMMA fp16]
    gemm_mma<false,true><<<dim3(EMB / 128, NTOK / 128), 256, GEMM_SMEM>>>(
        ff1, w2t, b_ff2, h1, nullptr, y, HID, EMB);

    // 7) out = LN2(y)
    ln2_kernel<<<NTOK, 256>>>(ln2_w, ln2_b, out);
}